// round 4
// baseline (speedup 1.0000x reference)
#include <cuda_runtime.h>
#include <math.h>

#define KK 4
#define BB 64
#define SS 50
#define DD 256
#define VV 40000
#define HH 4
#define DHD 64
#define BS (BB*SS)          // 3200
#define BSD (BS*DD)         // 819200
#define FFD (4*DD)          // 1024
#define NEGV (-1e9f)
#define SCL 0.125f          // 1/sqrt(64)

// -------------------- scratch (device globals, no allocation) ----------------
__device__ __align__(16) float g_hg[BSD];
__device__ __align__(16) float g_hloc[BSD];
__device__ __align__(16) float g_h[KK*BSD];      // h_keys accumulators
__device__ __align__(16) float g_x[BSD];
__device__ __align__(16) float g_q[BSD];
__device__ __align__(16) float g_k[BSD];
__device__ __align__(16) float g_v[BSD];
__device__ __align__(16) float g_o[BSD];
__device__ __align__(16) float g_ff[BS*FFD];
__device__ __align__(16) float g_hseq[BSD];

__device__ __forceinline__ float warp_sum(float v) {
    #pragma unroll
    for (int o = 16; o; o >>= 1) v += __shfl_xor_sync(0xffffffffu, v, o);
    return v;
}
__device__ __forceinline__ float warp_max(float v) {
    #pragma unroll
    for (int o = 16; o; o >>= 1) v = fmaxf(v, __shfl_xor_sync(0xffffffffu, v, o));
    return v;
}
__device__ __forceinline__ float gelu_f(float x) {
    float x3 = x * x * x;
    return 0.5f * x * (1.0f + tanhf(0.7978845608028654f * (x + 0.044715f * x3)));
}

// -------------------- gather hg = emb[items] ---------------------------------
__global__ void gather_hg_kernel(const float* __restrict__ emb_k,
                                 const int* __restrict__ items_k,
                                 float* __restrict__ hg) {
    int bs = blockIdx.x;
    int it = items_k[bs];
    hg[(size_t)bs * DD + threadIdx.x] = emb_k[(size_t)it * DD + threadIdx.x];
}

// -------------------- local aggregator (one block per batch b) ---------------
// dyn smem: hg[50*256] | a[4*256] | alpha[50*50]
__global__ void localagg_kernel(const float* __restrict__ hg,
                                const int* __restrict__ adj,
                                const float* __restrict__ agg_a_k,
                                float* __restrict__ hloc) {
    extern __shared__ float sm[];
    float* sm_hg = sm;               // 12800
    float* sm_a  = sm + 12800;       // 1024
    float* sm_al = sm + 13824;       // 2500
    int b = blockIdx.x;
    int tid = threadIdx.x;
    for (int t = tid; t < SS * DD; t += 256) sm_hg[t] = hg[(size_t)b * SS * DD + t];
    for (int t = tid; t < 4 * DD; t += 256)  sm_a[t] = agg_a_k[t];
    __syncthreads();

    int w = tid >> 5, lane = tid & 31;
    // relation-typed scores for present edges
    for (int p = w; p < SS * SS; p += 8) {
        int i = p / SS, j = p % SS;
        int r = adj[(size_t)b * SS * SS + p];
        float val = NEGV;
        if (r != 0) {
            const float* ar = sm_a + (r - 1) * DD;
            float acc = 0.0f;
            for (int d = lane; d < DD; d += 32)
                acc += sm_hg[i * DD + d] * sm_hg[j * DD + d] * ar[d];
            acc = warp_sum(acc);
            val = (acc >= 0.0f) ? acc : 0.2f * acc;   // leaky_relu 0.2
        }
        if (lane == 0) sm_al[p] = val;
    }
    __syncthreads();
    // row softmax (all-NEG rows -> uniform, matching jax)
    for (int i = w; i < SS; i += 8) {
        float v0 = (lane < SS) ? sm_al[i * SS + lane] : -INFINITY;
        float v1 = (lane + 32 < SS) ? sm_al[i * SS + lane + 32] : -INFINITY;
        float m = warp_max(fmaxf(v0, v1));
        float e0 = (lane < SS) ? expf(v0 - m) : 0.0f;
        float e1 = (lane + 32 < SS) ? expf(v1 - m) : 0.0f;
        float s = warp_sum(e0 + e1);
        float inv = 1.0f / s;
        if (lane < SS) sm_al[i * SS + lane] = e0 * inv;
        if (lane + 32 < SS) sm_al[i * SS + lane + 32] = e1 * inv;
    }
    __syncthreads();
    // h_local = alpha @ hg
    for (int idx = tid; idx < SS * DD; idx += 256) {
        int i = idx / DD, d = idx % DD;
        float acc = 0.0f;
        #pragma unroll 10
        for (int j = 0; j < SS; j++) acc += sm_al[i * SS + j] * sm_hg[j * DD + d];
        hloc[(size_t)b * SS * DD + idx] = acc;
    }
}

// -------------------- alias distribute ---------------------------------------
__global__ void alias_gather_kernel(const float* __restrict__ hloc,
                                    const int* __restrict__ alias,
                                    float* __restrict__ hout) {
    int bs = blockIdx.x;
    int b = bs / SS;
    int al = alias[bs];
    hout[(size_t)bs * DD + threadIdx.x] =
        hloc[((size_t)b * SS + al) * DD + threadIdx.x];
}

// -------------------- layernorm (population variance) ------------------------
__global__ void ln_kernel(const float* __restrict__ in,
                          const float* __restrict__ g,
                          const float* __restrict__ bta,
                          float* __restrict__ out) {
    __shared__ float s1[256], s2[256];
    int bs = blockIdx.x, d = threadIdx.x;
    float x = in[(size_t)bs * DD + d];
    s1[d] = x; s2[d] = x * x;
    __syncthreads();
    for (int st = 128; st > 0; st >>= 1) {
        if (d < st) { s1[d] += s1[d + st]; s2[d] += s2[d + st]; }
        __syncthreads();
    }
    float m = s1[0] * (1.0f / DD);
    float var = fmaxf(s2[0] * (1.0f / DD) - m * m, 0.0f);
    float inv = rsqrtf(var + 1e-5f);
    out[(size_t)bs * DD + d] = (x - m) * inv * g[d] + bta[d];
}

// -------------------- generic tiled SGEMM with residual/act epilogue ---------
// C[M,N] = act(A[M,K] @ B[K,N] + Res)  ;  M%64==0, N%64==0, K%16==0
#define GBM 64
#define GBN 64
#define GBK 16
__global__ void gemm_kernel(const float* __restrict__ A,
                            const float* __restrict__ Bm,
                            const float* __restrict__ Res,
                            float* __restrict__ C,
                            int M, int N, int Kd, int act) {
    __shared__ __align__(16) float As[GBK][GBM];
    __shared__ __align__(16) float Bs[GBK][GBN];
    int tid = threadIdx.x;
    int tx = tid & 15, ty = tid >> 4;
    int row0 = blockIdx.y * GBM, col0 = blockIdx.x * GBN;
    int aRow = tid >> 2, aCol = (tid & 3) * 4;
    int bRow = tid >> 4, bCol = (tid & 15) * 4;
    float acc[4][4] = {};
    for (int k0 = 0; k0 < Kd; k0 += GBK) {
        float4 av = *(const float4*)(A + (size_t)(row0 + aRow) * Kd + k0 + aCol);
        As[aCol + 0][aRow] = av.x; As[aCol + 1][aRow] = av.y;
        As[aCol + 2][aRow] = av.z; As[aCol + 3][aRow] = av.w;
        *(float4*)&Bs[bRow][bCol] =
            *(const float4*)(Bm + (size_t)(k0 + bRow) * N + col0 + bCol);
        __syncthreads();
        #pragma unroll
        for (int kk = 0; kk < GBK; kk++) {
            float4 a4 = *(float4*)&As[kk][ty * 4];
            float4 b4 = *(float4*)&Bs[kk][tx * 4];
            float ar[4] = {a4.x, a4.y, a4.z, a4.w};
            float br[4] = {b4.x, b4.y, b4.z, b4.w};
            #pragma unroll
            for (int i = 0; i < 4; i++)
                #pragma unroll
                for (int j = 0; j < 4; j++)
                    acc[i][j] += ar[i] * br[j];
        }
        __syncthreads();
    }
    #pragma unroll
    for (int i = 0; i < 4; i++) {
        int r = row0 + ty * 4 + i;
        #pragma unroll
        for (int j = 0; j < 4; j++) {
            int c = col0 + tx * 4 + j;
            float v = acc[i][j];
            if (Res) v += Res[(size_t)r * N + c];
            if (act == 1) v = gelu_f(v);
            C[(size_t)r * N + c] = v;
        }
    }
}

// -------------------- causal MHA (one block per (b,h)) -----------------------
__global__ void attn_kernel(const float* __restrict__ q,
                            const float* __restrict__ k,
                            const float* __restrict__ v,
                            float* __restrict__ o) {
    __shared__ float sq[SS * (DHD + 1)];
    __shared__ float sk[SS * (DHD + 1)];
    __shared__ float sv[SS * (DHD + 1)];
    __shared__ float sp[8 * 64];
    int b = blockIdx.x, h = blockIdx.y;
    for (int t = threadIdx.x; t < SS * DHD; t += 256) {
        int s = t / DHD, d = t % DHD;
        size_t gi = ((size_t)b * SS + s) * DD + h * DHD + d;
        int si = s * (DHD + 1) + d;
        sq[si] = q[gi]; sk[si] = k[gi]; sv[si] = v[gi];
    }
    __syncthreads();
    int w = threadIdx.x >> 5, lane = threadIdx.x & 31;
    for (int i = w; i < SS; i += 8) {
        float sc[2];
        #pragma unroll
        for (int jj = 0; jj < 2; jj++) {
            int j = lane + jj * 32;
            float val = NEGV;
            if (j < SS && j <= i) {
                float acc = 0.0f;
                #pragma unroll 16
                for (int d = 0; d < DHD; d++)
                    acc += sq[i * (DHD + 1) + d] * sk[j * (DHD + 1) + d];
                val = acc * SCL;
            }
            sc[jj] = val;
        }
        float m = warp_max(fmaxf(sc[0], sc[1]));
        float e0 = expf(sc[0] - m), e1 = expf(sc[1] - m);
        if (lane + 32 >= SS) e1 = 0.0f;
        float s = warp_sum(e0 + e1);
        float inv = 1.0f / s;
        sp[w * 64 + lane] = e0 * inv;
        if (lane + 32 < 64) sp[w * 64 + 32 + lane] = e1 * inv;
        __syncwarp();
        #pragma unroll
        for (int dd = 0; dd < 2; dd++) {
            int d = lane + dd * 32;
            float acc = 0.0f;
            #pragma unroll 10
            for (int j = 0; j < SS; j++)
                acc += sp[w * 64 + j] * sv[j * (DHD + 1) + d];
            o[((size_t)b * SS + i) * DD + h * DHD + d] = acc;
        }
    }
}

// -------------------- h_seq = mean_k emb[k][ids[k]] --------------------------
__global__ void hseq_kernel(const float* __restrict__ emb,
                            const int* __restrict__ ids,
                            float* __restrict__ hseq) {
    int bs = blockIdx.x, d = threadIdx.x;
    float acc = 0.0f;
    #pragma unroll
    for (int kk = 0; kk < KK; kk++) {
        int id = ids[(size_t)kk * BS + bs];
        acc += emb[(size_t)kk * VV * DD + (size_t)id * DD + d];
    }
    hseq[(size_t)bs * DD + d] = acc * 0.25f;
}

// -------------------- noisy top-2 gating + combine ---------------------------
__global__ void gate_kernel(const float* __restrict__ hseq,
                            const float* __restrict__ Wg,
                            const float* __restrict__ Wn,
                            const float* __restrict__ eps,
                            const float* __restrict__ hk,
                            float* __restrict__ out) {
    __shared__ float red[8 * 256];
    __shared__ float sg[KK];
    int bs = blockIdx.x, d = threadIdx.x;
    float hx = hseq[(size_t)bs * DD + d];
    #pragma unroll
    for (int kk = 0; kk < KK; kk++) {
        red[kk * 256 + d]       = hx * Wg[d * KK + kk];
        red[(4 + kk) * 256 + d] = hx * Wn[d * KK + kk];
    }
    __syncthreads();
    for (int st = 128; st > 0; st >>= 1) {
        if (d < st) {
            #pragma unroll
            for (int j = 0; j < 8; j++)
                red[j * 256 + d] += red[j * 256 + d + st];
        }
        __syncthreads();
    }
    if (d == 0) {
        float lg[KK];
        #pragma unroll
        for (int kk = 0; kk < KK; kk++) {
            float noise = red[(4 + kk) * 256];
            float sp = (noise > 0.0f) ? (noise + log1pf(expf(-noise)))
                                      : log1pf(expf(noise));
            lg[kk] = red[kk * 256] + sp * eps[(size_t)bs * KK + kk];
        }
        int i1 = 0; float v1 = lg[0];
        #pragma unroll
        for (int kk = 1; kk < KK; kk++) if (lg[kk] > v1) { v1 = lg[kk]; i1 = kk; }
        int i2 = -1; float v2 = -INFINITY;
        #pragma unroll
        for (int kk = 0; kk < KK; kk++)
            if (kk != i1 && lg[kk] > v2) { v2 = lg[kk]; i2 = kk; }
        float e2 = expf(v2 - v1);
        float den = 1.0f / (1.0f + e2);
        #pragma unroll
        for (int kk = 0; kk < KK; kk++) sg[kk] = 0.0f;
        sg[i1] = den;
        sg[i2] = e2 * den;
    }
    __syncthreads();
    float acc = 0.0f;
    #pragma unroll
    for (int kk = 0; kk < KK; kk++)
        acc += sg[kk] * hk[(size_t)kk * BSD + (size_t)bs * DD + d];
    out[(size_t)bs * DD + d] = acc;
}

// -------------------- launch -------------------------------------------------
extern "C" void kernel_launch(void* const* d_in, const int* in_sizes, int n_in,
                              void* d_out, int out_size) {
    const int*   ids   = (const int*)d_in[0];
    const int*   items = (const int*)d_in[1];
    const int*   adj   = (const int*)d_in[2];
    const int*   alias = (const int*)d_in[3];
    const float* eps   = (const float*)d_in[4];
    const float* emb   = (const float*)d_in[5];
    const float* agg_a = (const float*)d_in[6];
    const float* Wq    = (const float*)d_in[7];
    const float* Wk    = (const float*)d_in[8];
    const float* Wv    = (const float*)d_in[9];
    const float* Wo    = (const float*)d_in[10];
    const float* ln1g  = (const float*)d_in[11];
    const float* ln1b  = (const float*)d_in[12];
    const float* W1    = (const float*)d_in[13];
    const float* W2    = (const float*)d_in[14];
    const float* ln2g  = (const float*)d_in[15];
    const float* ln2b  = (const float*)d_in[16];
    const float* Wg    = (const float*)d_in[17];
    const float* Wn    = (const float*)d_in[18];
    float* out = (float*)d_out;

    float *p_hg, *p_hloc, *p_h, *p_x, *p_q, *p_k, *p_v, *p_o, *p_ff, *p_hseq;
    cudaGetSymbolAddress((void**)&p_hg,   g_hg);
    cudaGetSymbolAddress((void**)&p_hloc, g_hloc);
    cudaGetSymbolAddress((void**)&p_h,    g_h);
    cudaGetSymbolAddress((void**)&p_x,    g_x);
    cudaGetSymbolAddress((void**)&p_q,    g_q);
    cudaGetSymbolAddress((void**)&p_k,    g_k);
    cudaGetSymbolAddress((void**)&p_v,    g_v);
    cudaGetSymbolAddress((void**)&p_o,    g_o);
    cudaGetSymbolAddress((void**)&p_ff,   g_ff);
    cudaGetSymbolAddress((void**)&p_hseq, g_hseq);

    const int smem_agg = (SS * DD + 4 * DD + SS * SS) * sizeof(float);  // 65296
    cudaFuncSetAttribute(localagg_kernel,
                         cudaFuncAttributeMaxDynamicSharedMemorySize, smem_agg);

    hseq_kernel<<<BS, 256>>>(emb, ids, p_hseq);

    for (int k = 0; k < KK; k++) {
        const float* emb_k = emb + (size_t)k * VV * DD;
        float* hk = p_h + (size_t)k * BSD;

        gather_hg_kernel<<<BS, 256>>>(emb_k, items + (size_t)k * BS, p_hg);
        localagg_kernel<<<BB, 256, smem_agg>>>(p_hg, adj,
                                               agg_a + (size_t)k * 4 * DD, p_hloc);
        alias_gather_kernel<<<BS, 256>>>(p_hloc, alias, hk);

        ln_kernel<<<BS, 256>>>(hk, ln1g + k * DD, ln1b + k * DD, p_x);

        dim3 g1(DD / GBN, BS / GBM);
        gemm_kernel<<<g1, 256>>>(p_x, Wq + (size_t)k * DD * DD, nullptr, p_q,
                                 BS, DD, DD, 0);
        gemm_kernel<<<g1, 256>>>(p_x, Wk + (size_t)k * DD * DD, nullptr, p_k,
                                 BS, DD, DD, 0);
        gemm_kernel<<<g1, 256>>>(p_x, Wv + (size_t)k * DD * DD, nullptr, p_v,
                                 BS, DD, DD, 0);

        attn_kernel<<<dim3(BB, HH), 256>>>(p_q, p_k, p_v, p_o);

        gemm_kernel<<<g1, 256>>>(p_o, Wo + (size_t)k * DD * DD, hk, hk,
                                 BS, DD, DD, 0);

        ln_kernel<<<BS, 256>>>(hk, ln2g + k * DD, ln2b + k * DD, p_x);

        dim3 g2(FFD / GBN, BS / GBM);
        gemm_kernel<<<g2, 256>>>(p_x, W1 + (size_t)k * DD * FFD, nullptr, p_ff,
                                 BS, FFD, DD, 1);
        gemm_kernel<<<g1, 256>>>(p_ff, W2 + (size_t)k * FFD * DD, hk, hk,
                                 BS, DD, FFD, 0);
    }

    gate_kernel<<<BS, 256>>>(p_hseq, Wg, Wn, eps, p_h, out);
}

// round 5
// speedup vs baseline: 1.0032x; 1.0032x over previous
#include <cuda_runtime.h>
#include <math.h>

#define KK 4
#define BB 64
#define SS 50
#define DD 256
#define VV 40000
#define HH 4
#define DHD 64
#define BS (BB*SS)          // 3200
#define BSD (BS*DD)         // 819200
#define FFD (4*DD)          // 1024
#define NEGV (-1e9f)
#define SCL 0.125f          // 1/sqrt(64)

// -------------------- scratch (device globals, no allocation) ----------------
__device__ __align__(16) float g_hg[BSD];
__device__ __align__(16) float g_hloc[BSD];
__device__ __align__(16) float g_h[KK*BSD];      // h_keys accumulators
__device__ __align__(16) float g_x[BSD];
__device__ __align__(16) float g_q[BSD];
__device__ __align__(16) float g_k[BSD];
__device__ __align__(16) float g_v[BSD];
__device__ __align__(16) float g_o[BSD];
__device__ __align__(16) float g_ff[BS*FFD];
__device__ __align__(16) float g_hseq[BSD];

__device__ __forceinline__ float warp_sum(float v) {
    #pragma unroll
    for (int o = 16; o; o >>= 1) v += __shfl_xor_sync(0xffffffffu, v, o);
    return v;
}
__device__ __forceinline__ float warp_max(float v) {
    #pragma unroll
    for (int o = 16; o; o >>= 1) v = fmaxf(v, __shfl_xor_sync(0xffffffffu, v, o));
    return v;
}
__device__ __forceinline__ float gelu_f(float x) {
    float x3 = x * x * x;
    return 0.5f * x * (1.0f + tanhf(0.7978845608028654f * (x + 0.044715f * x3)));
}

// -------------------- gather hg = emb[items] ---------------------------------
__global__ void gather_hg_kernel(const float* __restrict__ emb_k,
                                 const int* __restrict__ items_k,
                                 float* __restrict__ hg) {
    int bs = blockIdx.x;
    int it = items_k[bs];
    hg[(size_t)bs * DD + threadIdx.x] = emb_k[(size_t)it * DD + threadIdx.x];
}

// -------------------- local aggregator (one block per batch b) ---------------
// dyn smem: hg[50*256] | a[4*256] | alpha[50*50]
__global__ void localagg_kernel(const float* __restrict__ hg,
                                const int* __restrict__ adj,
                                const float* __restrict__ agg_a_k,
                                float* __restrict__ hloc) {
    extern __shared__ float sm[];
    float* sm_hg = sm;               // 12800
    float* sm_a  = sm + 12800;       // 1024
    float* sm_al = sm + 13824;       // 2500
    int b = blockIdx.x;
    int tid = threadIdx.x;
    for (int t = tid; t < SS * DD; t += 256) sm_hg[t] = hg[(size_t)b * SS * DD + t];
    for (int t = tid; t < 4 * DD; t += 256)  sm_a[t] = agg_a_k[t];
    __syncthreads();

    int w = tid >> 5, lane = tid & 31;
    // relation-typed scores for present edges
    for (int p = w; p < SS * SS; p += 8) {
        int i = p / SS, j = p % SS;
        int r = adj[(size_t)b * SS * SS + p];
        float val = NEGV;
        if (r != 0) {
            const float* ar = sm_a + (r - 1) * DD;
            float acc = 0.0f;
            for (int d = lane; d < DD; d += 32)
                acc += sm_hg[i * DD + d] * sm_hg[j * DD + d] * ar[d];
            acc = warp_sum(acc);
            val = (acc >= 0.0f) ? acc : 0.2f * acc;   // leaky_relu 0.2
        }
        if (lane == 0) sm_al[p] = val;
    }
    __syncthreads();
    // row softmax (all-NEG rows -> uniform, matching jax)
    for (int i = w; i < SS; i += 8) {
        float v0 = (lane < SS) ? sm_al[i * SS + lane] : -INFINITY;
        float v1 = (lane + 32 < SS) ? sm_al[i * SS + lane + 32] : -INFINITY;
        float m = warp_max(fmaxf(v0, v1));
        float e0 = (lane < SS) ? expf(v0 - m) : 0.0f;
        float e1 = (lane + 32 < SS) ? expf(v1 - m) : 0.0f;
        float s = warp_sum(e0 + e1);
        float inv = 1.0f / s;
        if (lane < SS) sm_al[i * SS + lane] = e0 * inv;
        if (lane + 32 < SS) sm_al[i * SS + lane + 32] = e1 * inv;
    }
    __syncthreads();
    // h_local = alpha @ hg
    for (int idx = tid; idx < SS * DD; idx += 256) {
        int i = idx / DD, d = idx % DD;
        float acc = 0.0f;
        #pragma unroll 10
        for (int j = 0; j < SS; j++) acc += sm_al[i * SS + j] * sm_hg[j * DD + d];
        hloc[(size_t)b * SS * DD + idx] = acc;
    }
}

// -------------------- alias distribute ---------------------------------------
__global__ void alias_gather_kernel(const float* __restrict__ hloc,
                                    const int* __restrict__ alias,
                                    float* __restrict__ hout) {
    int bs = blockIdx.x;
    int b = bs / SS;
    int al = alias[bs];
    hout[(size_t)bs * DD + threadIdx.x] =
        hloc[((size_t)b * SS + al) * DD + threadIdx.x];
}

// -------------------- layernorm (population variance) ------------------------
__global__ void ln_kernel(const float* __restrict__ in,
                          const float* __restrict__ g,
                          const float* __restrict__ bta,
                          float* __restrict__ out) {
    __shared__ float s1[256], s2[256];
    int bs = blockIdx.x, d = threadIdx.x;
    float x = in[(size_t)bs * DD + d];
    s1[d] = x; s2[d] = x * x;
    __syncthreads();
    for (int st = 128; st > 0; st >>= 1) {
        if (d < st) { s1[d] += s1[d + st]; s2[d] += s2[d + st]; }
        __syncthreads();
    }
    float m = s1[0] * (1.0f / DD);
    float var = fmaxf(s2[0] * (1.0f / DD) - m * m, 0.0f);
    float inv = rsqrtf(var + 1e-5f);
    out[(size_t)bs * DD + d] = (x - m) * inv * g[d] + bta[d];
}

// -------------------- generic tiled SGEMM with residual/act epilogue ---------
// C[M,N] = act(A[M,K] @ B[K,N] + Res)  ;  M%64==0, N%64==0, K%16==0
#define GBM 64
#define GBN 64
#define GBK 16
__global__ void gemm_kernel(const float* __restrict__ A,
                            const float* __restrict__ Bm,
                            const float* __restrict__ Res,
                            float* __restrict__ C,
                            int M, int N, int Kd, int act) {
    __shared__ __align__(16) float As[GBK][GBM];
    __shared__ __align__(16) float Bs[GBK][GBN];
    int tid = threadIdx.x;
    int tx = tid & 15, ty = tid >> 4;
    int row0 = blockIdx.y * GBM, col0 = blockIdx.x * GBN;
    int aRow = tid >> 2, aCol = (tid & 3) * 4;
    int bRow = tid >> 4, bCol = (tid & 15) * 4;
    float acc[4][4] = {};
    for (int k0 = 0; k0 < Kd; k0 += GBK) {
        float4 av = *(const float4*)(A + (size_t)(row0 + aRow) * Kd + k0 + aCol);
        As[aCol + 0][aRow] = av.x; As[aCol + 1][aRow] = av.y;
        As[aCol + 2][aRow] = av.z; As[aCol + 3][aRow] = av.w;
        *(float4*)&Bs[bRow][bCol] =
            *(const float4*)(Bm + (size_t)(k0 + bRow) * N + col0 + bCol);
        __syncthreads();
        #pragma unroll
        for (int kk = 0; kk < GBK; kk++) {
            float4 a4 = *(float4*)&As[kk][ty * 4];
            float4 b4 = *(float4*)&Bs[kk][tx * 4];
            float ar[4] = {a4.x, a4.y, a4.z, a4.w};
            float br[4] = {b4.x, b4.y, b4.z, b4.w};
            #pragma unroll
            for (int i = 0; i < 4; i++)
                #pragma unroll
                for (int j = 0; j < 4; j++)
                    acc[i][j] += ar[i] * br[j];
        }
        __syncthreads();
    }
    #pragma unroll
    for (int i = 0; i < 4; i++) {
        int r = row0 + ty * 4 + i;
        #pragma unroll
        for (int j = 0; j < 4; j++) {
            int c = col0 + tx * 4 + j;
            float v = acc[i][j];
            if (Res) v += Res[(size_t)r * N + c];
            if (act == 1) v = gelu_f(v);
            C[(size_t)r * N + c] = v;
        }
    }
}

// -------------------- causal MHA (one block per (b,h)) -----------------------
__global__ void attn_kernel(const float* __restrict__ q,
                            const float* __restrict__ k,
                            const float* __restrict__ v,
                            float* __restrict__ o) {
    __shared__ float sq[SS * (DHD + 1)];
    __shared__ float sk[SS * (DHD + 1)];
    __shared__ float sv[SS * (DHD + 1)];
    __shared__ float sp[8 * 64];
    int b = blockIdx.x, h = blockIdx.y;
    for (int t = threadIdx.x; t < SS * DHD; t += 256) {
        int s = t / DHD, d = t % DHD;
        size_t gi = ((size_t)b * SS + s) * DD + h * DHD + d;
        int si = s * (DHD + 1) + d;
        sq[si] = q[gi]; sk[si] = k[gi]; sv[si] = v[gi];
    }
    __syncthreads();
    int w = threadIdx.x >> 5, lane = threadIdx.x & 31;
    for (int i = w; i < SS; i += 8) {
        float sc[2];
        #pragma unroll
        for (int jj = 0; jj < 2; jj++) {
            int j = lane + jj * 32;
            float val = NEGV;
            if (j < SS && j <= i) {
                float acc = 0.0f;
                #pragma unroll 16
                for (int d = 0; d < DHD; d++)
                    acc += sq[i * (DHD + 1) + d] * sk[j * (DHD + 1) + d];
                val = acc * SCL;
            }
            sc[jj] = val;
        }
        float m = warp_max(fmaxf(sc[0], sc[1]));
        float e0 = expf(sc[0] - m), e1 = expf(sc[1] - m);
        if (lane + 32 >= SS) e1 = 0.0f;
        float s = warp_sum(e0 + e1);
        float inv = 1.0f / s;
        sp[w * 64 + lane] = e0 * inv;
        if (lane + 32 < 64) sp[w * 64 + 32 + lane] = e1 * inv;
        __syncwarp();
        #pragma unroll
        for (int dd = 0; dd < 2; dd++) {
            int d = lane + dd * 32;
            float acc = 0.0f;
            #pragma unroll 10
            for (int j = 0; j < SS; j++)
                acc += sp[w * 64 + j] * sv[j * (DHD + 1) + d];
            o[((size_t)b * SS + i) * DD + h * DHD + d] = acc;
        }
    }
}

// -------------------- h_seq = mean_k emb[k][ids[k]] --------------------------
__global__ void hseq_kernel(const float* __restrict__ emb,
                            const int* __restrict__ ids,
                            float* __restrict__ hseq) {
    int bs = blockIdx.x, d = threadIdx.x;
    float acc = 0.0f;
    #pragma unroll
    for (int kk = 0; kk < KK; kk++) {
        int id = ids[(size_t)kk * BS + bs];
        acc += emb[(size_t)kk * VV * DD + (size_t)id * DD + d];
    }
    hseq[(size_t)bs * DD + d] = acc * 0.25f;
}

// -------------------- noisy top-2 gating + combine ---------------------------
__global__ void gate_kernel(const float* __restrict__ hseq,
                            const float* __restrict__ Wg,
                            const float* __restrict__ Wn,
                            const float* __restrict__ eps,
                            const float* __restrict__ hk,
                            float* __restrict__ out) {
    __shared__ float red[8 * 256];
    __shared__ float sg[KK];
    int bs = blockIdx.x, d = threadIdx.x;
    float hx = hseq[(size_t)bs * DD + d];
    #pragma unroll
    for (int kk = 0; kk < KK; kk++) {
        red[kk * 256 + d]       = hx * Wg[d * KK + kk];
        red[(4 + kk) * 256 + d] = hx * Wn[d * KK + kk];
    }
    __syncthreads();
    for (int st = 128; st > 0; st >>= 1) {
        if (d < st) {
            #pragma unroll
            for (int j = 0; j < 8; j++)
                red[j * 256 + d] += red[j * 256 + d + st];
        }
        __syncthreads();
    }
    if (d == 0) {
        float lg[KK];
        #pragma unroll
        for (int kk = 0; kk < KK; kk++) {
            float noise = red[(4 + kk) * 256];
            float sp = (noise > 0.0f) ? (noise + log1pf(expf(-noise)))
                                      : log1pf(expf(noise));
            lg[kk] = red[kk * 256] + sp * eps[(size_t)bs * KK + kk];
        }
        int i1 = 0; float v1 = lg[0];
        #pragma unroll
        for (int kk = 1; kk < KK; kk++) if (lg[kk] > v1) { v1 = lg[kk]; i1 = kk; }
        int i2 = -1; float v2 = -INFINITY;
        #pragma unroll
        for (int kk = 0; kk < KK; kk++)
            if (kk != i1 && lg[kk] > v2) { v2 = lg[kk]; i2 = kk; }
        float e2 = expf(v2 - v1);
        float den = 1.0f / (1.0f + e2);
        #pragma unroll
        for (int kk = 0; kk < KK; kk++) sg[kk] = 0.0f;
        sg[i1] = den;
        sg[i2] = e2 * den;
    }
    __syncthreads();
    float acc = 0.0f;
    #pragma unroll
    for (int kk = 0; kk < KK; kk++)
        acc += sg[kk] * hk[(size_t)kk * BSD + (size_t)bs * DD + d];
    out[(size_t)bs * DD + d] = acc;
}

// -------------------- launch -------------------------------------------------
extern "C" void kernel_launch(void* const* d_in, const int* in_sizes, int n_in,
                              void* d_out, int out_size) {
    const int*   ids   = (const int*)d_in[0];
    const int*   items = (const int*)d_in[1];
    const int*   adj   = (const int*)d_in[2];
    const int*   alias = (const int*)d_in[3];
    const float* eps   = (const float*)d_in[4];
    const float* emb   = (const float*)d_in[5];
    const float* agg_a = (const float*)d_in[6];
    const float* Wq    = (const float*)d_in[7];
    const float* Wk    = (const float*)d_in[8];
    const float* Wv    = (const float*)d_in[9];
    const float* Wo    = (const float*)d_in[10];
    const float* ln1g  = (const float*)d_in[11];
    const float* ln1b  = (const float*)d_in[12];
    const float* W1    = (const float*)d_in[13];
    const float* W2    = (const float*)d_in[14];
    const float* ln2g  = (const float*)d_in[15];
    const float* ln2b  = (const float*)d_in[16];
    const float* Wg    = (const float*)d_in[17];
    const float* Wn    = (const float*)d_in[18];
    float* out = (float*)d_out;

    float *p_hg, *p_hloc, *p_h, *p_x, *p_q, *p_k, *p_v, *p_o, *p_ff, *p_hseq;
    cudaGetSymbolAddress((void**)&p_hg,   g_hg);
    cudaGetSymbolAddress((void**)&p_hloc, g_hloc);
    cudaGetSymbolAddress((void**)&p_h,    g_h);
    cudaGetSymbolAddress((void**)&p_x,    g_x);
    cudaGetSymbolAddress((void**)&p_q,    g_q);
    cudaGetSymbolAddress((void**)&p_k,    g_k);
    cudaGetSymbolAddress((void**)&p_v,    g_v);
    cudaGetSymbolAddress((void**)&p_o,    g_o);
    cudaGetSymbolAddress((void**)&p_ff,   g_ff);
    cudaGetSymbolAddress((void**)&p_hseq, g_hseq);

    const int smem_agg = (SS * DD + 4 * DD + SS * SS) * sizeof(float);  // 65296
    cudaFuncSetAttribute(localagg_kernel,
                         cudaFuncAttributeMaxDynamicSharedMemorySize, smem_agg);

    hseq_kernel<<<BS, 256>>>(emb, ids, p_hseq);

    for (int k = 0; k < KK; k++) {
        const float* emb_k = emb + (size_t)k * VV * DD;
        float* hk = p_h + (size_t)k * BSD;

        gather_hg_kernel<<<BS, 256>>>(emb_k, items + (size_t)k * BS, p_hg);
        localagg_kernel<<<BB, 256, smem_agg>>>(p_hg, adj,
                                               agg_a + (size_t)k * 4 * DD, p_hloc);
        alias_gather_kernel<<<BS, 256>>>(p_hloc, alias, hk);

        ln_kernel<<<BS, 256>>>(hk, ln1g + k * DD, ln1b + k * DD, p_x);

        dim3 g1(DD / GBN, BS / GBM);
        gemm_kernel<<<g1, 256>>>(p_x, Wq + (size_t)k * DD * DD, nullptr, p_q,
                                 BS, DD, DD, 0);
        gemm_kernel<<<g1, 256>>>(p_x, Wk + (size_t)k * DD * DD, nullptr, p_k,
                                 BS, DD, DD, 0);
        gemm_kernel<<<g1, 256>>>(p_x, Wv + (size_t)k * DD * DD, nullptr, p_v,
                                 BS, DD, DD, 0);

        attn_kernel<<<dim3(BB, HH), 256>>>(p_q, p_k, p_v, p_o);

        gemm_kernel<<<g1, 256>>>(p_o, Wo + (size_t)k * DD * DD, hk, hk,
                                 BS, DD, DD, 0);

        ln_kernel<<<BS, 256>>>(hk, ln2g + k * DD, ln2b + k * DD, p_x);

        dim3 g2(FFD / GBN, BS / GBM);
        gemm_kernel<<<g2, 256>>>(p_x, W1 + (size_t)k * DD * FFD, nullptr, p_ff,
                                 BS, FFD, DD, 1);
        gemm_kernel<<<g1, 256>>>(p_ff, W2 + (size_t)k * FFD * DD, hk, hk,
                                 BS, DD, FFD, 0);
    }

    gate_kernel<<<BS, 256>>>(p_hseq, Wg, Wn, eps, p_h, out);
}

// round 6
// speedup vs baseline: 1.8212x; 1.8153x over previous
#include <cuda_runtime.h>
#include <math.h>

#define KK 4
#define BB 64
#define SS 50
#define DD 256
#define VV 40000
#define HH 4
#define DHD 64
#define BS (BB*SS)          // 3200
#define BSD (BS*DD)         // 819200
#define FFD (4*DD)          // 1024
#define NEGV (-1e9f)
#define SCL 0.125f          // 1/sqrt(64)

// -------------------- scratch (device globals, no allocation) ----------------
__device__ __align__(16) float g_hloc[KK*BSD];
__device__ __align__(16) float g_h[KK*BSD];      // h_keys accumulators
__device__ __align__(16) float g_x[KK*BSD];
__device__ __align__(16) float g_q[KK*BSD];
__device__ __align__(16) float g_k[KK*BSD];
__device__ __align__(16) float g_v[KK*BSD];
__device__ __align__(16) float g_o[KK*BSD];
__device__ __align__(16) float g_ff[(size_t)KK*BS*FFD];
__device__ __align__(16) float g_hseq[BSD];

__device__ __forceinline__ float warp_sum(float v) {
    #pragma unroll
    for (int o = 16; o; o >>= 1) v += __shfl_xor_sync(0xffffffffu, v, o);
    return v;
}
__device__ __forceinline__ float warp_max(float v) {
    #pragma unroll
    for (int o = 16; o; o >>= 1) v = fmaxf(v, __shfl_xor_sync(0xffffffffu, v, o));
    return v;
}
__device__ __forceinline__ float gelu_f(float x) {
    float x3 = x * x * x;
    return 0.5f * x * (1.0f + tanhf(0.7978845608028654f * (x + 0.044715f * x3)));
}

// -------------------- local aggregator, fused emb-gather, batched over k -----
// grid (BB, KK); dyn smem: hg[50*256] | a[4*256] | alpha[50*50]
__global__ void localagg_kernel(const float* __restrict__ emb,
                                const int* __restrict__ items,
                                const int* __restrict__ adj,
                                const float* __restrict__ agg_a,
                                float* __restrict__ hloc) {
    extern __shared__ float sm[];
    float* sm_hg = sm;               // 12800 floats
    float* sm_a  = sm + 12800;       // 1024
    float* sm_al = sm + 13824;       // 2500
    int b = blockIdx.x;
    int key = blockIdx.y;
    int tid = threadIdx.x;
    const float* emb_k = emb + (size_t)key * VV * DD;
    const int* items_k = items + (size_t)key * BS + (size_t)b * SS;
    // fused gather: hg = emb[items]
    for (int t = tid; t < SS * DD; t += 256) {
        int s = t >> 8, d = t & 255;
        int it = items_k[s];
        sm_hg[t] = emb_k[(size_t)it * DD + d];
    }
    for (int t = tid; t < 4 * DD; t += 256)
        sm_a[t] = agg_a[(size_t)key * 4 * DD + t];
    __syncthreads();

    int w = tid >> 5, lane = tid & 31;
    // relation-typed scores for present edges (float4 vectorized)
    for (int p = w; p < SS * SS; p += 8) {
        int i = p / SS, j = p % SS;
        int r = adj[(size_t)b * SS * SS + p];
        float val = NEGV;
        if (r != 0) {
            const float4* hi4 = (const float4*)(sm_hg + i * DD);
            const float4* hj4 = (const float4*)(sm_hg + j * DD);
            const float4* ar4 = (const float4*)(sm_a + (r - 1) * DD);
            float acc = 0.0f;
            #pragma unroll
            for (int t = 0; t < 2; t++) {
                int idx = lane + t * 32;
                float4 a = hi4[idx], bb = hj4[idx], c = ar4[idx];
                acc = fmaf(a.x * bb.x, c.x, acc);
                acc = fmaf(a.y * bb.y, c.y, acc);
                acc = fmaf(a.z * bb.z, c.z, acc);
                acc = fmaf(a.w * bb.w, c.w, acc);
            }
            acc = warp_sum(acc);
            val = (acc >= 0.0f) ? acc : 0.2f * acc;   // leaky_relu 0.2
        }
        if (lane == 0) sm_al[p] = val;
    }
    __syncthreads();
    // row softmax (all-NEG rows -> uniform, matching jax)
    for (int i = w; i < SS; i += 8) {
        float v0 = (lane < SS) ? sm_al[i * SS + lane] : -INFINITY;
        float v1 = (lane + 32 < SS) ? sm_al[i * SS + lane + 32] : -INFINITY;
        float m = warp_max(fmaxf(v0, v1));
        float e0 = (lane < SS) ? expf(v0 - m) : 0.0f;
        float e1 = (lane + 32 < SS) ? expf(v1 - m) : 0.0f;
        float s = warp_sum(e0 + e1);
        float inv = 1.0f / s;
        if (lane < SS) sm_al[i * SS + lane] = e0 * inv;
        if (lane + 32 < SS) sm_al[i * SS + lane + 32] = e1 * inv;
    }
    __syncthreads();
    // h_local = alpha @ hg
    float* outp = hloc + (size_t)key * BSD + (size_t)b * SS * DD;
    for (int idx = tid; idx < SS * DD; idx += 256) {
        int i = idx >> 8, d = idx & 255;
        float acc = 0.0f;
        #pragma unroll 10
        for (int j = 0; j < SS; j++) acc += sm_al[i * SS + j] * sm_hg[j * DD + d];
        outp[idx] = acc;
    }
}

// -------------------- batched LayerNorm (optional alias-gather + copy) -------
// grid (BS, KK), 256 threads
__global__ void ln_bat_kernel(const float* __restrict__ in,
                              const int* __restrict__ alias,   // may be null
                              const float* __restrict__ g,
                              const float* __restrict__ bta,
                              float* __restrict__ copy_out,     // may be null
                              float* __restrict__ x) {
    int key = blockIdx.y, bs = blockIdx.x, d = threadIdx.x;
    size_t src;
    if (alias) {
        int b = bs / SS;
        src = (size_t)key * BSD + ((size_t)b * SS + alias[bs]) * DD + d;
    } else {
        src = (size_t)key * BSD + (size_t)bs * DD + d;
    }
    float v = in[src];
    size_t dst = (size_t)key * BSD + (size_t)bs * DD + d;
    if (copy_out) copy_out[dst] = v;
    __shared__ float sm[8], sv[8];
    int w = d >> 5, lane = d & 31;
    float s = warp_sum(v), q = warp_sum(v * v);
    if (lane == 0) { sm[w] = s; sv[w] = q; }
    __syncthreads();
    float tm = 0.0f, tv = 0.0f;
    #pragma unroll
    for (int j = 0; j < 8; j++) { tm += sm[j]; tv += sv[j]; }
    float mean = tm * (1.0f / DD);
    float var = fmaxf(tv * (1.0f / DD) - mean * mean, 0.0f);
    float inv = rsqrtf(var + 1e-5f);
    x[dst] = (v - mean) * inv * g[key * DD + d] + bta[key * DD + d];
}

// -------------------- double-buffered tiled SGEMM core -----------------------
// C[M,N] = act(A[M,K] @ B[K,N] + Res)  ;  M%64==0, N%64==0, K%16==0
#define GBM 64
#define GBN 64
#define GBK 16
__device__ __forceinline__ void gemm_tile(const float* __restrict__ A,
                                          const float* __restrict__ Bm,
                                          const float* __restrict__ Res,
                                          float* __restrict__ C,
                                          int N, int Kd, int act) {
    __shared__ __align__(16) float As[2][GBK][GBM];
    __shared__ __align__(16) float Bs[2][GBK][GBN];
    int tid = threadIdx.x;
    int tx = tid & 15, ty = tid >> 4;
    int row0 = blockIdx.y * GBM, col0 = blockIdx.x * GBN;
    int aRow = tid >> 2, aCol = (tid & 3) * 4;
    int bRow = tid >> 4, bCol = (tid & 15) * 4;
    const float* Aptr = A + (size_t)(row0 + aRow) * Kd + aCol;
    const float* Bptr = Bm + (size_t)bRow * N + col0 + bCol;

    float4 a_ld = *(const float4*)Aptr;
    float4 b_ld = *(const float4*)Bptr;
    As[0][aCol + 0][aRow] = a_ld.x; As[0][aCol + 1][aRow] = a_ld.y;
    As[0][aCol + 2][aRow] = a_ld.z; As[0][aCol + 3][aRow] = a_ld.w;
    *(float4*)&Bs[0][bRow][bCol] = b_ld;
    __syncthreads();

    float acc[4][4] = {};
    int buf = 0;
    for (int k0 = GBK; k0 <= Kd; k0 += GBK) {
        bool has = (k0 < Kd);
        if (has) {
            a_ld = *(const float4*)(Aptr + k0);
            b_ld = *(const float4*)(Bptr + (size_t)k0 * N);
        }
        #pragma unroll
        for (int kk = 0; kk < GBK; kk++) {
            float4 a4 = *(float4*)&As[buf][kk][ty * 4];
            float4 b4 = *(float4*)&Bs[buf][kk][tx * 4];
            float ar[4] = {a4.x, a4.y, a4.z, a4.w};
            float br[4] = {b4.x, b4.y, b4.z, b4.w};
            #pragma unroll
            for (int i = 0; i < 4; i++)
                #pragma unroll
                for (int j = 0; j < 4; j++)
                    acc[i][j] = fmaf(ar[i], br[j], acc[i][j]);
        }
        if (has) {
            int nb = buf ^ 1;
            As[nb][aCol + 0][aRow] = a_ld.x; As[nb][aCol + 1][aRow] = a_ld.y;
            As[nb][aCol + 2][aRow] = a_ld.z; As[nb][aCol + 3][aRow] = a_ld.w;
            *(float4*)&Bs[nb][bRow][bCol] = b_ld;
            __syncthreads();
            buf = nb;
        }
    }
    #pragma unroll
    for (int i = 0; i < 4; i++) {
        int r = row0 + ty * 4 + i;
        float4 v = make_float4(acc[i][0], acc[i][1], acc[i][2], acc[i][3]);
        size_t off = (size_t)r * N + col0 + tx * 4;
        if (Res) {
            float4 rv = *(const float4*)(Res + off);
            v.x += rv.x; v.y += rv.y; v.z += rv.z; v.w += rv.w;
        }
        if (act == 1) {
            v.x = gelu_f(v.x); v.y = gelu_f(v.y);
            v.z = gelu_f(v.z); v.w = gelu_f(v.w);
        }
        *(float4*)(C + off) = v;
    }
}

// batched generic: blockIdx.z selects slice via element strides
__global__ void gemm_bat_kernel(const float* __restrict__ A, size_t sA,
                                const float* __restrict__ Bm, size_t sB,
                                const float* __restrict__ Res, size_t sR,
                                float* __restrict__ C, size_t sC,
                                int N, int Kd, int act) {
    size_t z = blockIdx.z;
    gemm_tile(A + z * sA, Bm + z * sB,
              Res ? Res + z * sR : nullptr, C + z * sC, N, Kd, act);
}

// QKV fused-batched: blockIdx.z = key*3 + {0:Q,1:K,2:V}
__global__ void gemm_qkv_kernel(const float* __restrict__ x,
                                const float* __restrict__ Wq,
                                const float* __restrict__ Wk,
                                const float* __restrict__ Wv,
                                float* __restrict__ q,
                                float* __restrict__ k,
                                float* __restrict__ v) {
    int z = blockIdx.z;
    int key = z / 3, m = z - key * 3;
    const float* A = x + (size_t)key * BSD;
    const float* B = (m == 0 ? Wq : m == 1 ? Wk : Wv) + (size_t)key * DD * DD;
    float* C = (m == 0 ? q : m == 1 ? k : v) + (size_t)key * BSD;
    gemm_tile(A, B, nullptr, C, DD, DD, 0);
}

// -------------------- causal MHA, batched over k: grid (BB, HH, KK) ----------
__global__ void attn_kernel(const float* __restrict__ q,
                            const float* __restrict__ k,
                            const float* __restrict__ v,
                            float* __restrict__ o) {
    __shared__ float sq[SS * (DHD + 1)];
    __shared__ float sk[SS * (DHD + 1)];
    __shared__ float sv[SS * (DHD + 1)];
    __shared__ float sp[8 * 64];
    int b = blockIdx.x, h = blockIdx.y;
    size_t kb = (size_t)blockIdx.z * BSD;
    for (int t = threadIdx.x; t < SS * DHD; t += 256) {
        int s = t / DHD, d = t % DHD;
        size_t gi = kb + ((size_t)b * SS + s) * DD + h * DHD + d;
        int si = s * (DHD + 1) + d;
        sq[si] = q[gi]; sk[si] = k[gi]; sv[si] = v[gi];
    }
    __syncthreads();
    int w = threadIdx.x >> 5, lane = threadIdx.x & 31;
    for (int i = w; i < SS; i += 8) {
        float sc[2];
        #pragma unroll
        for (int jj = 0; jj < 2; jj++) {
            int j = lane + jj * 32;
            float val = NEGV;
            if (j < SS && j <= i) {
                float acc = 0.0f;
                #pragma unroll 16
                for (int d = 0; d < DHD; d++)
                    acc += sq[i * (DHD + 1) + d] * sk[j * (DHD + 1) + d];
                val = acc * SCL;
            }
            sc[jj] = val;
        }
        float m = warp_max(fmaxf(sc[0], sc[1]));
        float e0 = expf(sc[0] - m), e1 = expf(sc[1] - m);
        if (lane + 32 >= SS) e1 = 0.0f;
        float s = warp_sum(e0 + e1);
        float inv = 1.0f / s;
        sp[w * 64 + lane] = e0 * inv;
        if (lane + 32 < 64) sp[w * 64 + 32 + lane] = e1 * inv;
        __syncwarp();
        #pragma unroll
        for (int dd = 0; dd < 2; dd++) {
            int d = lane + dd * 32;
            float acc = 0.0f;
            #pragma unroll 10
            for (int j = 0; j < SS; j++)
                acc += sp[w * 64 + j] * sv[j * (DHD + 1) + d];
            o[kb + ((size_t)b * SS + i) * DD + h * DHD + d] = acc;
        }
    }
}

// -------------------- h_seq = mean_k emb[k][ids[k]] --------------------------
__global__ void hseq_kernel(const float* __restrict__ emb,
                            const int* __restrict__ ids,
                            float* __restrict__ hseq) {
    int bs = blockIdx.x, d = threadIdx.x;
    float acc = 0.0f;
    #pragma unroll
    for (int kk = 0; kk < KK; kk++) {
        int id = ids[(size_t)kk * BS + bs];
        acc += emb[(size_t)kk * VV * DD + (size_t)id * DD + d];
    }
    hseq[(size_t)bs * DD + d] = acc * 0.25f;
}

// -------------------- noisy top-2 gating + combine ---------------------------
__global__ void gate_kernel(const float* __restrict__ hseq,
                            const float* __restrict__ Wg,
                            const float* __restrict__ Wn,
                            const float* __restrict__ eps,
                            const float* __restrict__ hk,
                            float* __restrict__ out) {
    __shared__ float red[8 * 256];
    __shared__ float sg[KK];
    int bs = blockIdx.x, d = threadIdx.x;
    float hx = hseq[(size_t)bs * DD + d];
    #pragma unroll
    for (int kk = 0; kk < KK; kk++) {
        red[kk * 256 + d]       = hx * Wg[d * KK + kk];
        red[(4 + kk) * 256 + d] = hx * Wn[d * KK + kk];
    }
    __syncthreads();
    for (int st = 128; st > 0; st >>= 1) {
        if (d < st) {
            #pragma unroll
            for (int j = 0; j < 8; j++)
                red[j * 256 + d] += red[j * 256 + d + st];
        }
        __syncthreads();
    }
    if (d == 0) {
        float lg[KK];
        #pragma unroll
        for (int kk = 0; kk < KK; kk++) {
            float noise = red[(4 + kk) * 256];
            float sp = (noise > 0.0f) ? (noise + log1pf(expf(-noise)))
                                      : log1pf(expf(noise));
            lg[kk] = red[kk * 256] + sp * eps[(size_t)bs * KK + kk];
        }
        int i1 = 0; float v1 = lg[0];
        #pragma unroll
        for (int kk = 1; kk < KK; kk++) if (lg[kk] > v1) { v1 = lg[kk]; i1 = kk; }
        int i2 = -1; float v2 = -INFINITY;
        #pragma unroll
        for (int kk = 0; kk < KK; kk++)
            if (kk != i1 && lg[kk] > v2) { v2 = lg[kk]; i2 = kk; }
        float e2 = expf(v2 - v1);
        float den = 1.0f / (1.0f + e2);
        #pragma unroll
        for (int kk = 0; kk < KK; kk++) sg[kk] = 0.0f;
        sg[i1] = den;
        sg[i2] = e2 * den;
    }
    __syncthreads();
    float acc = 0.0f;
    #pragma unroll
    for (int kk = 0; kk < KK; kk++)
        acc += sg[kk] * hk[(size_t)kk * BSD + (size_t)bs * DD + d];
    out[(size_t)bs * DD + d] = acc;
}

// -------------------- launch -------------------------------------------------
extern "C" void kernel_launch(void* const* d_in, const int* in_sizes, int n_in,
                              void* d_out, int out_size) {
    const int*   ids   = (const int*)d_in[0];
    const int*   items = (const int*)d_in[1];
    const int*   adj   = (const int*)d_in[2];
    const int*   alias = (const int*)d_in[3];
    const float* eps   = (const float*)d_in[4];
    const float* emb   = (const float*)d_in[5];
    const float* agg_a = (const float*)d_in[6];
    const float* Wq    = (const float*)d_in[7];
    const float* Wk    = (const float*)d_in[8];
    const float* Wv    = (const float*)d_in[9];
    const float* Wo    = (const float*)d_in[10];
    const float* ln1g  = (const float*)d_in[11];
    const float* ln1b  = (const float*)d_in[12];
    const float* W1    = (const float*)d_in[13];
    const float* W2    = (const float*)d_in[14];
    const float* ln2g  = (const float*)d_in[15];
    const float* ln2b  = (const float*)d_in[16];
    const float* Wg    = (const float*)d_in[17];
    const float* Wn    = (const float*)d_in[18];
    float* out = (float*)d_out;

    float *p_hloc, *p_h, *p_x, *p_q, *p_k, *p_v, *p_o, *p_ff, *p_hseq;
    cudaGetSymbolAddress((void**)&p_hloc, g_hloc);
    cudaGetSymbolAddress((void**)&p_h,    g_h);
    cudaGetSymbolAddress((void**)&p_x,    g_x);
    cudaGetSymbolAddress((void**)&p_q,    g_q);
    cudaGetSymbolAddress((void**)&p_k,    g_k);
    cudaGetSymbolAddress((void**)&p_v,    g_v);
    cudaGetSymbolAddress((void**)&p_o,    g_o);
    cudaGetSymbolAddress((void**)&p_ff,   g_ff);
    cudaGetSymbolAddress((void**)&p_hseq, g_hseq);

    const int smem_agg = (SS * DD + 4 * DD + SS * SS) * sizeof(float);  // 65296
    cudaFuncSetAttribute(localagg_kernel,
                         cudaFuncAttributeMaxDynamicSharedMemorySize, smem_agg);

    const size_t sW = (size_t)DD * DD;
    const size_t sFF = (size_t)BS * FFD;

    hseq_kernel<<<BS, 256>>>(emb, ids, p_hseq);

    // graph aggregation + alias + LN1, all keys at once
    localagg_kernel<<<dim3(BB, KK), 256, smem_agg>>>(emb, items, adj, agg_a, p_hloc);
    ln_bat_kernel<<<dim3(BS, KK), 256>>>(p_hloc, alias, ln1g, ln1b, p_h, p_x);

    // QKV for all keys (12 GEMMs in one launch)
    gemm_qkv_kernel<<<dim3(DD / GBN, BS / GBM, KK * 3), 256>>>(
        p_x, Wq, Wk, Wv, p_q, p_k, p_v);

    attn_kernel<<<dim3(BB, HH, KK), 256>>>(p_q, p_k, p_v, p_o);

    // h += O @ Wo   (all keys)
    gemm_bat_kernel<<<dim3(DD / GBN, BS / GBM, KK), 256>>>(
        p_o, (size_t)BSD, Wo, sW, p_h, (size_t)BSD, p_h, (size_t)BSD, DD, DD, 0);

    // LN2 (all keys)
    ln_bat_kernel<<<dim3(BS, KK), 256>>>(p_h, nullptr, ln2g, ln2b, nullptr, p_x);

    // FFN1: gelu(x @ W1)  (all keys)
    gemm_bat_kernel<<<dim3(FFD / GBN, BS / GBM, KK), 256>>>(
        p_x, (size_t)BSD, W1, (size_t)DD * FFD, nullptr, 0, p_ff, sFF, FFD, DD, 1);

    // FFN2: h += ff @ W2  (all keys)
    gemm_bat_kernel<<<dim3(DD / GBN, BS / GBM, KK), 256>>>(
        p_ff, sFF, W2, (size_t)FFD * DD, p_h, (size_t)BSD, p_h, (size_t)BSD, DD, FFD, 0);

    gate_kernel<<<BS, 256>>>(p_hseq, Wg, Wn, eps, p_h, out);
}

// round 7
// speedup vs baseline: 2.0311x; 1.1152x over previous
#include <cuda_runtime.h>
#include <math.h>

#define KK 4
#define BB 64
#define SS 50
#define DD 256
#define VV 40000
#define HH 4
#define DHD 64
#define BS (BB*SS)          // 3200
#define BSD (BS*DD)         // 819200
#define FFD (4*DD)          // 1024
#define NEGV (-1e9f)
#define SCL 0.125f          // 1/sqrt(64)

// -------------------- scratch (device globals, no allocation) ----------------
__device__ __align__(16) float g_hloc[KK*BSD];
__device__ __align__(16) float g_h[KK*BSD];      // h_keys accumulators
__device__ __align__(16) float g_x[KK*BSD];
__device__ __align__(16) float g_q[KK*BSD];
__device__ __align__(16) float g_k[KK*BSD];
__device__ __align__(16) float g_v[KK*BSD];
__device__ __align__(16) float g_o[KK*BSD];
__device__ __align__(16) float g_ff[(size_t)KK*BS*FFD];
__device__ __align__(16) float g_hseq[BSD];

__device__ __forceinline__ float warp_sum(float v) {
    #pragma unroll
    for (int o = 16; o; o >>= 1) v += __shfl_xor_sync(0xffffffffu, v, o);
    return v;
}
__device__ __forceinline__ float warp_max(float v) {
    #pragma unroll
    for (int o = 16; o; o >>= 1) v = fmaxf(v, __shfl_xor_sync(0xffffffffu, v, o));
    return v;
}
__device__ __forceinline__ float gelu_f(float x) {
    float x3 = x * x * x;
    return 0.5f * x * (1.0f + tanhf(0.7978845608028654f * (x + 0.044715f * x3)));
}

// -------------------- local aggregator, fused emb-gather, batched over k -----
// grid (BB, KK); dyn smem: hg[50*256] | a[4*256] | alpha[50*50]
__global__ void localagg_kernel(const float* __restrict__ emb,
                                const int* __restrict__ items,
                                const int* __restrict__ adj,
                                const float* __restrict__ agg_a,
                                float* __restrict__ hloc) {
    extern __shared__ float sm[];
    float* sm_hg = sm;               // 12800 floats
    float* sm_a  = sm + 12800;       // 1024
    float* sm_al = sm + 13824;       // 2500
    int b = blockIdx.x;
    int key = blockIdx.y;
    int tid = threadIdx.x;
    const float* emb_k = emb + (size_t)key * VV * DD;
    const int* items_k = items + (size_t)key * BS + (size_t)b * SS;
    // fused gather: hg = emb[items]
    for (int t = tid; t < SS * DD; t += 256) {
        int s = t >> 8, d = t & 255;
        int it = items_k[s];
        sm_hg[t] = emb_k[(size_t)it * DD + d];
    }
    for (int t = tid; t < 4 * DD; t += 256)
        sm_a[t] = agg_a[(size_t)key * 4 * DD + t];
    __syncthreads();

    int w = tid >> 5, lane = tid & 31;
    // relation-typed scores for present edges (float4 vectorized)
    for (int p = w; p < SS * SS; p += 8) {
        int i = p / SS, j = p % SS;
        int r = adj[(size_t)b * SS * SS + p];
        float val = NEGV;
        if (r != 0) {
            const float4* hi4 = (const float4*)(sm_hg + i * DD);
            const float4* hj4 = (const float4*)(sm_hg + j * DD);
            const float4* ar4 = (const float4*)(sm_a + (r - 1) * DD);
            float acc = 0.0f;
            #pragma unroll
            for (int t = 0; t < 2; t++) {
                int idx = lane + t * 32;
                float4 a = hi4[idx], bb = hj4[idx], c = ar4[idx];
                acc = fmaf(a.x * bb.x, c.x, acc);
                acc = fmaf(a.y * bb.y, c.y, acc);
                acc = fmaf(a.z * bb.z, c.z, acc);
                acc = fmaf(a.w * bb.w, c.w, acc);
            }
            acc = warp_sum(acc);
            val = (acc >= 0.0f) ? acc : 0.2f * acc;   // leaky_relu 0.2
        }
        if (lane == 0) sm_al[p] = val;
    }
    __syncthreads();
    // row softmax (all-NEG rows -> uniform, matching jax)
    for (int i = w; i < SS; i += 8) {
        float v0 = (lane < SS) ? sm_al[i * SS + lane] : -INFINITY;
        float v1 = (lane + 32 < SS) ? sm_al[i * SS + lane + 32] : -INFINITY;
        float m = warp_max(fmaxf(v0, v1));
        float e0 = (lane < SS) ? expf(v0 - m) : 0.0f;
        float e1 = (lane + 32 < SS) ? expf(v1 - m) : 0.0f;
        float s = warp_sum(e0 + e1);
        float inv = 1.0f / s;
        if (lane < SS) sm_al[i * SS + lane] = e0 * inv;
        if (lane + 32 < SS) sm_al[i * SS + lane + 32] = e1 * inv;
    }
    __syncthreads();
    // h_local = alpha @ hg
    float* outp = hloc + (size_t)key * BSD + (size_t)b * SS * DD;
    for (int idx = tid; idx < SS * DD; idx += 256) {
        int i = idx >> 8, d = idx & 255;
        float acc = 0.0f;
        #pragma unroll 10
        for (int j = 0; j < SS; j++) acc += sm_al[i * SS + j] * sm_hg[j * DD + d];
        outp[idx] = acc;
    }
}

// -------------------- batched LayerNorm (optional alias-gather + copy) -------
// grid (BS, KK), 256 threads
__global__ void ln_bat_kernel(const float* __restrict__ in,
                              const int* __restrict__ alias,   // may be null
                              const float* __restrict__ g,
                              const float* __restrict__ bta,
                              float* __restrict__ copy_out,     // may be null
                              float* __restrict__ x) {
    int key = blockIdx.y, bs = blockIdx.x, d = threadIdx.x;
    size_t src;
    if (alias) {
        int b = bs / SS;
        src = (size_t)key * BSD + ((size_t)b * SS + alias[bs]) * DD + d;
    } else {
        src = (size_t)key * BSD + (size_t)bs * DD + d;
    }
    float v = in[src];
    size_t dst = (size_t)key * BSD + (size_t)bs * DD + d;
    if (copy_out) copy_out[dst] = v;
    __shared__ float sm[8], sv[8];
    int w = d >> 5, lane = d & 31;
    float s = warp_sum(v), q = warp_sum(v * v);
    if (lane == 0) { sm[w] = s; sv[w] = q; }
    __syncthreads();
    float tm = 0.0f, tv = 0.0f;
    #pragma unroll
    for (int j = 0; j < 8; j++) { tm += sm[j]; tv += sv[j]; }
    float mean = tm * (1.0f / DD);
    float var = fmaxf(tv * (1.0f / DD) - mean * mean, 0.0f);
    float inv = rsqrtf(var + 1e-5f);
    x[dst] = (v - mean) * inv * g[key * DD + d] + bta[key * DD + d];
}

// -------------------- 128x128x8 double-buffered SGEMM, 8x8 microtile ---------
// C[M,N] = act(A[M,K] @ B[K,N] + Res)  ;  M%128==0, N%128==0, K%8==0
#define TBM 128
#define TBN 128
#define TBK 8
__device__ __forceinline__ void gemm_tile128(const float* __restrict__ A,
                                             const float* __restrict__ Bm,
                                             const float* __restrict__ Res,
                                             float* __restrict__ C,
                                             int N, int Kd, int act) {
    __shared__ __align__(16) float As[2][TBK][TBM];
    __shared__ __align__(16) float Bs[2][TBK][TBN];
    int tid = threadIdx.x;
    int tx = tid & 15, ty = tid >> 4;
    int row0 = blockIdx.y * TBM, col0 = blockIdx.x * TBN;
    int aRow = tid >> 1, aCol = (tid & 1) * 4;     // A: 128 rows x 8 cols, float4/thread
    int bRow = tid >> 5, bCol = (tid & 31) * 4;    // B: 8 rows x 128 cols, float4/thread
    const float* Aptr = A + (size_t)(row0 + aRow) * Kd + aCol;
    const float* Bptr = Bm + (size_t)bRow * N + col0 + bCol;

    float4 a_ld = *(const float4*)Aptr;
    float4 b_ld = *(const float4*)Bptr;
    As[0][aCol + 0][aRow] = a_ld.x; As[0][aCol + 1][aRow] = a_ld.y;
    As[0][aCol + 2][aRow] = a_ld.z; As[0][aCol + 3][aRow] = a_ld.w;
    *(float4*)&Bs[0][bRow][bCol] = b_ld;
    __syncthreads();

    float acc[8][8] = {};
    int buf = 0;
    for (int k0 = TBK; k0 <= Kd; k0 += TBK) {
        bool has = (k0 < Kd);
        if (has) {
            a_ld = *(const float4*)(Aptr + k0);
            b_ld = *(const float4*)(Bptr + (size_t)k0 * N);
        }
        #pragma unroll
        for (int kk = 0; kk < TBK; kk++) {
            float4 a0 = *(float4*)&As[buf][kk][ty * 4];
            float4 a1 = *(float4*)&As[buf][kk][64 + ty * 4];
            float4 b0 = *(float4*)&Bs[buf][kk][tx * 4];
            float4 b1 = *(float4*)&Bs[buf][kk][64 + tx * 4];
            float ar[8] = {a0.x, a0.y, a0.z, a0.w, a1.x, a1.y, a1.z, a1.w};
            float br[8] = {b0.x, b0.y, b0.z, b0.w, b1.x, b1.y, b1.z, b1.w};
            #pragma unroll
            for (int i = 0; i < 8; i++)
                #pragma unroll
                for (int j = 0; j < 8; j++)
                    acc[i][j] = fmaf(ar[i], br[j], acc[i][j]);
        }
        if (has) {
            int nb = buf ^ 1;
            As[nb][aCol + 0][aRow] = a_ld.x; As[nb][aCol + 1][aRow] = a_ld.y;
            As[nb][aCol + 2][aRow] = a_ld.z; As[nb][aCol + 3][aRow] = a_ld.w;
            *(float4*)&Bs[nb][bRow][bCol] = b_ld;
            __syncthreads();
            buf = nb;
        }
    }
    #pragma unroll
    for (int ih = 0; ih < 2; ih++) {
        #pragma unroll
        for (int i = 0; i < 4; i++) {
            int r = row0 + ih * 64 + ty * 4 + i;
            #pragma unroll
            for (int jh = 0; jh < 2; jh++) {
                int ai = ih * 4 + i;
                float4 v = make_float4(acc[ai][jh * 4 + 0], acc[ai][jh * 4 + 1],
                                       acc[ai][jh * 4 + 2], acc[ai][jh * 4 + 3]);
                size_t off = (size_t)r * N + col0 + jh * 64 + tx * 4;
                if (Res) {
                    float4 rv = *(const float4*)(Res + off);
                    v.x += rv.x; v.y += rv.y; v.z += rv.z; v.w += rv.w;
                }
                if (act == 1) {
                    v.x = gelu_f(v.x); v.y = gelu_f(v.y);
                    v.z = gelu_f(v.z); v.w = gelu_f(v.w);
                }
                *(float4*)(C + off) = v;
            }
        }
    }
}

// batched generic: blockIdx.z selects slice via element strides
__global__ void __launch_bounds__(256, 2)
gemm_bat_kernel(const float* __restrict__ A, size_t sA,
                const float* __restrict__ Bm, size_t sB,
                const float* __restrict__ Res, size_t sR,
                float* __restrict__ C, size_t sC,
                int N, int Kd, int act) {
    size_t z = blockIdx.z;
    gemm_tile128(A + z * sA, Bm + z * sB,
                 Res ? Res + z * sR : nullptr, C + z * sC, N, Kd, act);
}

// QKV fused-batched: blockIdx.z = key*3 + {0:Q,1:K,2:V}
__global__ void __launch_bounds__(256, 2)
gemm_qkv_kernel(const float* __restrict__ x,
                const float* __restrict__ Wq,
                const float* __restrict__ Wk,
                const float* __restrict__ Wv,
                float* __restrict__ q,
                float* __restrict__ k,
                float* __restrict__ v) {
    int z = blockIdx.z;
    int key = z / 3, m = z - key * 3;
    const float* A = x + (size_t)key * BSD;
    const float* B = (m == 0 ? Wq : m == 1 ? Wk : Wv) + (size_t)key * DD * DD;
    float* C = (m == 0 ? q : m == 1 ? k : v) + (size_t)key * BSD;
    gemm_tile128(A, B, nullptr, C, DD, DD, 0);
}

// -------------------- causal MHA, batched over k: grid (BB, HH, KK) ----------
__global__ void attn_kernel(const float* __restrict__ q,
                            const float* __restrict__ k,
                            const float* __restrict__ v,
                            float* __restrict__ o) {
    __shared__ float sq[SS * (DHD + 1)];
    __shared__ float sk[SS * (DHD + 1)];
    __shared__ float sv[SS * (DHD + 1)];
    __shared__ float sp[8 * 64];
    int b = blockIdx.x, h = blockIdx.y;
    size_t kb = (size_t)blockIdx.z * BSD;
    for (int t = threadIdx.x; t < SS * DHD; t += 256) {
        int s = t / DHD, d = t % DHD;
        size_t gi = kb + ((size_t)b * SS + s) * DD + h * DHD + d;
        int si = s * (DHD + 1) + d;
        sq[si] = q[gi]; sk[si] = k[gi]; sv[si] = v[gi];
    }
    __syncthreads();
    int w = threadIdx.x >> 5, lane = threadIdx.x & 31;
    for (int i = w; i < SS; i += 8) {
        float sc[2];
        #pragma unroll
        for (int jj = 0; jj < 2; jj++) {
            int j = lane + jj * 32;
            float val = NEGV;
            if (j < SS && j <= i) {
                float acc = 0.0f;
                #pragma unroll 16
                for (int d = 0; d < DHD; d++)
                    acc += sq[i * (DHD + 1) + d] * sk[j * (DHD + 1) + d];
                val = acc * SCL;
            }
            sc[jj] = val;
        }
        float m = warp_max(fmaxf(sc[0], sc[1]));
        float e0 = expf(sc[0] - m), e1 = expf(sc[1] - m);
        if (lane + 32 >= SS) e1 = 0.0f;
        float s = warp_sum(e0 + e1);
        float inv = 1.0f / s;
        sp[w * 64 + lane] = e0 * inv;
        if (lane + 32 < 64) sp[w * 64 + 32 + lane] = e1 * inv;
        __syncwarp();
        #pragma unroll
        for (int dd = 0; dd < 2; dd++) {
            int d = lane + dd * 32;
            float acc = 0.0f;
            #pragma unroll 10
            for (int j = 0; j < SS; j++)
                acc += sp[w * 64 + j] * sv[j * (DHD + 1) + d];
            o[kb + ((size_t)b * SS + i) * DD + h * DHD + d] = acc;
        }
    }
}

// -------------------- h_seq = mean_k emb[k][ids[k]] --------------------------
__global__ void hseq_kernel(const float* __restrict__ emb,
                            const int* __restrict__ ids,
                            float* __restrict__ hseq) {
    int bs = blockIdx.x, d = threadIdx.x;
    float acc = 0.0f;
    #pragma unroll
    for (int kk = 0; kk < KK; kk++) {
        int id = ids[(size_t)kk * BS + bs];
        acc += emb[(size_t)kk * VV * DD + (size_t)id * DD + d];
    }
    hseq[(size_t)bs * DD + d] = acc * 0.25f;
}

// -------------------- noisy top-2 gating + combine ---------------------------
__global__ void gate_kernel(const float* __restrict__ hseq,
                            const float* __restrict__ Wg,
                            const float* __restrict__ Wn,
                            const float* __restrict__ eps,
                            const float* __restrict__ hk,
                            float* __restrict__ out) {
    __shared__ float red[8 * 256];
    __shared__ float sg[KK];
    int bs = blockIdx.x, d = threadIdx.x;
    float hx = hseq[(size_t)bs * DD + d];
    #pragma unroll
    for (int kk = 0; kk < KK; kk++) {
        red[kk * 256 + d]       = hx * Wg[d * KK + kk];
        red[(4 + kk) * 256 + d] = hx * Wn[d * KK + kk];
    }
    __syncthreads();
    for (int st = 128; st > 0; st >>= 1) {
        if (d < st) {
            #pragma unroll
            for (int j = 0; j < 8; j++)
                red[j * 256 + d] += red[j * 256 + d + st];
        }
        __syncthreads();
    }
    if (d == 0) {
        float lg[KK];
        #pragma unroll
        for (int kk = 0; kk < KK; kk++) {
            float noise = red[(4 + kk) * 256];
            float sp = (noise > 0.0f) ? (noise + log1pf(expf(-noise)))
                                      : log1pf(expf(noise));
            lg[kk] = red[kk * 256] + sp * eps[(size_t)bs * KK + kk];
        }
        int i1 = 0; float v1 = lg[0];
        #pragma unroll
        for (int kk = 1; kk < KK; kk++) if (lg[kk] > v1) { v1 = lg[kk]; i1 = kk; }
        int i2 = -1; float v2 = -INFINITY;
        #pragma unroll
        for (int kk = 0; kk < KK; kk++)
            if (kk != i1 && lg[kk] > v2) { v2 = lg[kk]; i2 = kk; }
        float e2 = expf(v2 - v1);
        float den = 1.0f / (1.0f + e2);
        #pragma unroll
        for (int kk = 0; kk < KK; kk++) sg[kk] = 0.0f;
        sg[i1] = den;
        sg[i2] = e2 * den;
    }
    __syncthreads();
    float acc = 0.0f;
    #pragma unroll
    for (int kk = 0; kk < KK; kk++)
        acc += sg[kk] * hk[(size_t)kk * BSD + (size_t)bs * DD + d];
    out[(size_t)bs * DD + d] = acc;
}

// -------------------- launch -------------------------------------------------
extern "C" void kernel_launch(void* const* d_in, const int* in_sizes, int n_in,
                              void* d_out, int out_size) {
    const int*   ids   = (const int*)d_in[0];
    const int*   items = (const int*)d_in[1];
    const int*   adj   = (const int*)d_in[2];
    const int*   alias = (const int*)d_in[3];
    const float* eps   = (const float*)d_in[4];
    const float* emb   = (const float*)d_in[5];
    const float* agg_a = (const float*)d_in[6];
    const float* Wq    = (const float*)d_in[7];
    const float* Wk    = (const float*)d_in[8];
    const float* Wv    = (const float*)d_in[9];
    const float* Wo    = (const float*)d_in[10];
    const float* ln1g  = (const float*)d_in[11];
    const float* ln1b  = (const float*)d_in[12];
    const float* W1    = (const float*)d_in[13];
    const float* W2    = (const float*)d_in[14];
    const float* ln2g  = (const float*)d_in[15];
    const float* ln2b  = (const float*)d_in[16];
    const float* Wg    = (const float*)d_in[17];
    const float* Wn    = (const float*)d_in[18];
    float* out = (float*)d_out;

    float *p_hloc, *p_h, *p_x, *p_q, *p_k, *p_v, *p_o, *p_ff, *p_hseq;
    cudaGetSymbolAddress((void**)&p_hloc, g_hloc);
    cudaGetSymbolAddress((void**)&p_h,    g_h);
    cudaGetSymbolAddress((void**)&p_x,    g_x);
    cudaGetSymbolAddress((void**)&p_q,    g_q);
    cudaGetSymbolAddress((void**)&p_k,    g_k);
    cudaGetSymbolAddress((void**)&p_v,    g_v);
    cudaGetSymbolAddress((void**)&p_o,    g_o);
    cudaGetSymbolAddress((void**)&p_ff,   g_ff);
    cudaGetSymbolAddress((void**)&p_hseq, g_hseq);

    const int smem_agg = (SS * DD + 4 * DD + SS * SS) * sizeof(float);  // 65296
    cudaFuncSetAttribute(localagg_kernel,
                         cudaFuncAttributeMaxDynamicSharedMemorySize, smem_agg);

    const size_t sW = (size_t)DD * DD;
    const size_t sFF = (size_t)BS * FFD;

    hseq_kernel<<<BS, 256>>>(emb, ids, p_hseq);

    // graph aggregation + alias + LN1, all keys at once
    localagg_kernel<<<dim3(BB, KK), 256, smem_agg>>>(emb, items, adj, agg_a, p_hloc);
    ln_bat_kernel<<<dim3(BS, KK), 256>>>(p_hloc, alias, ln1g, ln1b, p_h, p_x);

    // QKV for all keys (12 GEMMs in one launch)
    gemm_qkv_kernel<<<dim3(DD / TBN, BS / TBM, KK * 3), 256>>>(
        p_x, Wq, Wk, Wv, p_q, p_k, p_v);

    attn_kernel<<<dim3(BB, HH, KK), 256>>>(p_q, p_k, p_v, p_o);

    // h += O @ Wo   (all keys)
    gemm_bat_kernel<<<dim3(DD / TBN, BS / TBM, KK), 256>>>(
        p_o, (size_t)BSD, Wo, sW, p_h, (size_t)BSD, p_h, (size_t)BSD, DD, DD, 0);

    // LN2 (all keys)
    ln_bat_kernel<<<dim3(BS, KK), 256>>>(p_h, nullptr, ln2g, ln2b, nullptr, p_x);

    // FFN1: gelu(x @ W1)  (all keys)
    gemm_bat_kernel<<<dim3(FFD / TBN, BS / TBM, KK), 256>>>(
        p_x, (size_t)BSD, W1, (size_t)DD * FFD, nullptr, 0, p_ff, sFF, FFD, DD, 1);

    // FFN2: h += ff @ W2  (all keys)
    gemm_bat_kernel<<<dim3(DD / TBN, BS / TBM, KK), 256>>>(
        p_ff, sFF, W2, (size_t)FFD * DD, p_h, (size_t)BSD, p_h, (size_t)BSD, DD, FFD, 0);

    gate_kernel<<<BS, 256>>>(p_hseq, Wg, Wn, eps, p_h, out);
}